// round 16
// baseline (speedup 1.0000x reference)
#include <cuda_runtime.h>
#include <math.h>
#include <stdint.h>

#define B_  4
#define S_  2048
#define D_  640
#define H_  10
#define KD_ 64
#define BH_ (B_*H_)
#define BS_ (B_*S_)

// Scratch (allocation-free rule: __device__ globals)
__device__ __align__(16) float g_q[BH_*S_*KD_];   // [b,h,s,kd]
__device__ __align__(16) float g_k[BH_*S_*KD_];   // [b,h,s,kd]
__device__ __align__(16) float g_vT[BH_*KD_*S_];  // [b,h,kd,s]  (transposed V)
__device__ __align__(16) float g_z[BS_*H_*KD_];   // [b,s,h,kd] = [8192, 640]

// m16n8k16 bf16 mma (Q,K projection, split-bf16)
__device__ __forceinline__ void mma_bf16(float* d,
                                         const uint32_t* a, const uint32_t* b,
                                         const float* c) {
    asm volatile(
        "mma.sync.aligned.m16n8k16.row.col.f32.bf16.bf16.f32 "
        "{%0,%1,%2,%3}, {%4,%5,%6,%7}, {%8,%9}, {%10,%11,%12,%13};"
        : "=f"(d[0]), "=f"(d[1]), "=f"(d[2]), "=f"(d[3])
        : "r"(a[0]), "r"(a[1]), "r"(a[2]), "r"(a[3]),
          "r"(b[0]), "r"(b[1]),
          "f"(c[0]), "f"(c[1]), "f"(c[2]), "f"(c[3]));
}

// m16n8k16 fp16 mma (V/out projection, attention S and PV)
__device__ __forceinline__ void mma_fp16(float* d,
                                         const uint32_t* a, const uint32_t* b,
                                         const float* c) {
    asm volatile(
        "mma.sync.aligned.m16n8k16.row.col.f32.f16.f16.f32 "
        "{%0,%1,%2,%3}, {%4,%5,%6,%7}, {%8,%9}, {%10,%11,%12,%13};"
        : "=f"(d[0]), "=f"(d[1]), "=f"(d[2]), "=f"(d[3])
        : "r"(a[0]), "r"(a[1]), "r"(a[2]), "r"(a[3]),
          "r"(b[0]), "r"(b[1]),
          "f"(c[0]), "f"(c[1]), "f"(c[2]), "f"(c[3]));
}

// pack two floats into fp16x2 (lo in low 16 bits)
__device__ __forceinline__ uint32_t pack_f16x2(float lo, float hi) {
    uint32_t r;
    asm("cvt.rn.f16x2.f32 %0, %1, %2;" : "=r"(r) : "f"(hi), "f"(lo));
    return r;
}

// Split two fp32 into packed bf16x2 hi and lo (3-term split source).
__device__ __forceinline__ void split_bf16x2(float v0, float v1,
                                             uint32_t& h, uint32_t& l) {
    uint32_t hh;
    asm("cvt.rn.bf16x2.f32 %0, %1, %2;" : "=r"(hh) : "f"(v1), "f"(v0));
    const float f0 = __uint_as_float(hh << 16);
    const float f1 = __uint_as_float(hh & 0xFFFF0000u);
    const float l0 = v0 - f0;
    const float l1 = v1 - f1;
    uint32_t ll;
    asm("cvt.rn.bf16x2.f32 %0, %1, %2;" : "=r"(ll) : "f"(l1), "f"(l0));
    h = hh; l = ll;
}

__device__ __forceinline__ uint32_t smem_u32(const void* p) {
    uint32_t a;
    asm("{ .reg .u64 t; cvta.to.shared.u64 t, %1; cvt.u32.u64 %0, t; }"
        : "=r"(a) : "l"(p));
    return a;
}
__device__ __forceinline__ void cp_async16(uint32_t dst, const void* src) {
    asm volatile("cp.async.cg.shared.global [%0], [%1], 16;"
                 :: "r"(dst), "l"(src));
}
#define CP_COMMIT()  asm volatile("cp.async.commit_group;" ::: "memory")
#define CP_WAIT(n)   asm volatile("cp.async.wait_group %0;" :: "n"(n) : "memory")

#define PADA 40
#define PADB 132
#define SA_F (128 * PADA)
#define SB_F (32 * PADB)
#define STG_F (SA_F + SB_F)
#define SMEM_G (2 * STG_F * 4)

// ---------------------------------------------------------------------------
// Unified pipelined GEMM on m16n8k16 tensor cores (proven R12).
// SPLIT 3: split-bf16 (Q,K). SPLIT 1: single fp16 (V, out).
// V (t==2) is written TRANSPOSED into g_vT[b,h,kd,s].
// ---------------------------------------------------------------------------
template<int SPLIT, int MODE>
__global__ __launch_bounds__(256) void gemm_tc(const float* __restrict__ Asrc,
                                               const float* __restrict__ W0,
                                               const float* __restrict__ W1,
                                               const float* __restrict__ W2,
                                               float* __restrict__ outp,
                                               int n_base)
{
    extern __shared__ float smf[];
    const uint32_t sbase = smem_u32(smf);

    const float* Aptr = (MODE == 1) ? (const float*)g_z : Asrc;

    const int tid = threadIdx.x;
    const int wid = tid >> 5;
    const int lid = tid & 31;
    const int g   = lid >> 2;
    const int tg  = lid & 3;
    const int wy  = wid & 3;
    const int wx  = wid >> 2;

    const int m0 = blockIdx.y * 128;
    const int n0 = n_base + blockIdx.x * 128;

    const float* W;
    int ha = 0, t = 0;
    if (MODE == 0) {
        t  = n0 / 640;
        W  = (t == 0) ? W0 : ((t == 1) ? W1 : W2);
        ha = (n0 % 640) >> 6;
    } else {
        W = W0;
    }

    auto load_stage = [&](int stage, int k0) {
        const uint32_t sb = sbase + (uint32_t)stage * STG_F * 4;
        #pragma unroll
        for (int i = 0; i < 4; i++) {
            const int e  = i * 256 + tid;
            const int r  = e >> 3;
            const int c4 = (e & 7) * 4;
            cp_async16(sb + (uint32_t)(r * PADA + c4) * 4,
                       Aptr + (size_t)(m0 + r) * D_ + k0 + c4);
        }
        #pragma unroll
        for (int i = 0; i < 4; i++) {
            const int e  = i * 256 + tid;
            const int k  = e >> 5;
            const int c4 = (e & 31) * 4;
            const float* src;
            if (MODE == 0) {
                const int h  = ha + (c4 >> 6);
                const int kd = c4 & 63;
                src = W + ((size_t)h * D_ + k0 + k) * KD_ + kd;
            } else {
                src = W + (size_t)(k0 + k) * D_ + n0 + c4;
            }
            cp_async16(sb + (uint32_t)(SA_F + k * PADB + c4) * 4, src);
        }
        CP_COMMIT();
    };

    float acc[2][8][4];
    #pragma unroll
    for (int r2 = 0; r2 < 2; r2++)
        #pragma unroll
        for (int nt = 0; nt < 8; nt++)
            #pragma unroll
            for (int e = 0; e < 4; e++) acc[r2][nt][e] = 0.f;

    const int NK = D_ / 32;   // 20
    load_stage(0, 0);

    for (int ki = 0; ki < NK; ki++) {
        const int cur = ki & 1;
        if (ki + 1 < NK) {
            load_stage((ki + 1) & 1, (ki + 1) * 32);
            CP_WAIT(1);
        } else {
            CP_WAIT(0);
        }
        __syncthreads();

        const float* As = smf + cur * STG_F;
        const float* Bs = As + SA_F;

        #pragma unroll
        for (int kk = 0; kk < 2; kk++) {
            const int kc = kk * 16;
            uint32_t bh[8][2], bl[8][2];
            #pragma unroll
            for (int nt = 0; nt < 8; nt++) {
                const int col = wx * 64 + nt * 8 + g;
                const float v0 = Bs[(kc + 2*tg)     * PADB + col];
                const float v1 = Bs[(kc + 2*tg + 1) * PADB + col];
                const float v2 = Bs[(kc + 2*tg + 8) * PADB + col];
                const float v3 = Bs[(kc + 2*tg + 9) * PADB + col];
                if (SPLIT == 3) {
                    split_bf16x2(v0, v1, bh[nt][0], bl[nt][0]);
                    split_bf16x2(v2, v3, bh[nt][1], bl[nt][1]);
                } else {
                    bh[nt][0] = pack_f16x2(v0, v1);
                    bh[nt][1] = pack_f16x2(v2, v3);
                }
            }
            #pragma unroll
            for (int r2 = 0; r2 < 2; r2++) {
                const int rb = wy * 32 + r2 * 16;
                uint32_t ah[4], al[4];
                {
                    const float2 p0 = *(const float2*)&As[(rb + g)     * PADA + kc + 2*tg];
                    const float2 p1 = *(const float2*)&As[(rb + g + 8) * PADA + kc + 2*tg];
                    const float2 p2 = *(const float2*)&As[(rb + g)     * PADA + kc + 8 + 2*tg];
                    const float2 p3 = *(const float2*)&As[(rb + g + 8) * PADA + kc + 8 + 2*tg];
                    if (SPLIT == 3) {
                        split_bf16x2(p0.x, p0.y, ah[0], al[0]);
                        split_bf16x2(p1.x, p1.y, ah[1], al[1]);
                        split_bf16x2(p2.x, p2.y, ah[2], al[2]);
                        split_bf16x2(p3.x, p3.y, ah[3], al[3]);
                    } else {
                        ah[0] = pack_f16x2(p0.x, p0.y);
                        ah[1] = pack_f16x2(p1.x, p1.y);
                        ah[2] = pack_f16x2(p2.x, p2.y);
                        ah[3] = pack_f16x2(p3.x, p3.y);
                    }
                }
                #pragma unroll
                for (int nt = 0; nt < 8; nt++) {
                    if (SPLIT == 3) {
                        mma_bf16(acc[r2][nt], ah, bh[nt], acc[r2][nt]);
                        mma_bf16(acc[r2][nt], ah, bl[nt], acc[r2][nt]);
                        mma_bf16(acc[r2][nt], al, bh[nt], acc[r2][nt]);
                    } else {
                        mma_fp16(acc[r2][nt], ah, bh[nt], acc[r2][nt]);
                    }
                }
            }
        }
        __syncthreads();
    }

    if (MODE == 0) {
        #pragma unroll
        for (int r2 = 0; r2 < 2; r2++) {
            const int m0r = m0 + wy * 32 + r2 * 16 + g;
            #pragma unroll
            for (int nt = 0; nt < 8; nt++) {
                const int col = wx * 64 + nt * 8 + 2 * tg;
                const int n   = n0 + col;
                const int h2  = (n % 640) >> 6;
                const int kd2 = n & 63;
                if (t == 2) {
                    // V: write transposed into g_vT[b,h,kd,s]
                    #pragma unroll
                    for (int rr = 0; rr < 2; rr++) {
                        const int m = m0r + rr * 8;
                        const int b = m >> 11, s = m & 2047;
                        float* dst = g_vT + ((size_t)(b * H_ + h2) * KD_ + kd2) * S_ + s;
                        dst[0]  = acc[r2][nt][rr * 2];
                        dst[S_] = acc[r2][nt][rr * 2 + 1];
                    }
                } else {
                    float* G = (t == 0) ? g_q : g_k;
                    #pragma unroll
                    for (int rr = 0; rr < 2; rr++) {
                        const int m = m0r + rr * 8;
                        const int b = m >> 11, s = m & 2047;
                        float* dst = G + (((size_t)(b * H_ + h2) * S_ + s) * KD_) + kd2;
                        *(float2*)dst = make_float2(acc[r2][nt][rr * 2],
                                                    acc[r2][nt][rr * 2 + 1]);
                    }
                }
            }
        }
    } else {
        #pragma unroll
        for (int r2 = 0; r2 < 2; r2++) {
            const int m0r = m0 + wy * 32 + r2 * 16 + g;
            #pragma unroll
            for (int nt = 0; nt < 8; nt++) {
                const int col = n0 + wx * 64 + nt * 8 + 2 * tg;
                *(float2*)(outp + (size_t)m0r * D_ + col)
                    = make_float2(acc[r2][nt][0], acc[r2][nt][1]);
                *(float2*)(outp + (size_t)(m0r + 8) * D_ + col)
                    = make_float2(acc[r2][nt][2], acc[r2][nt][3]);
            }
        }
    }
}

// ---------------------------------------------------------------------------
// Kernel 2: BARRIER-FREE flash attention. No SMEM. Q fragments loaded once
// to registers; K and V^T fragments read as contiguous float2 LDG + pack.
// fp16 S (m16n8k16) + fp16 PV, exp bias 8, fp32 accum. R14 numerics exactly.
// ---------------------------------------------------------------------------
#define EXP_BIAS 8.0f

__global__ __launch_bounds__(128, 3) void attn_mma()
{
    const int tid = threadIdx.x;
    const int wid = tid >> 5;
    const int lid = tid & 31;
    const int g   = lid >> 2;
    const int tg  = lid & 3;

    const int bh = blockIdx.y;
    const int b  = bh / H_;
    const int h  = bh % H_;
    const int q0 = blockIdx.x * 128;
    const size_t base = (size_t)bh * S_ * KD_;
    const int rowbase = wid * 32;

    // thread-fixed fragment base pointers
    // K frag (nt, kk, j): kptr + nt*512 + kk*16 + j*8   (+ kt*64 per tile)
    const float* kptr = g_k + base + (size_t)g * KD_ + 2 * tg;
    // V^T frag (nt, kc, j): vptr + nt*8*S_ + kc*16 + j*8 (+ kt per tile)
    const float* vptr = g_vT + (size_t)bh * KD_ * S_ + (size_t)g * S_ + 2 * tg;

    // Q fragments -> registers (pre-scaled by 1/8, fp16-packed)
    uint32_t qf[2][4][4];
    {
        const float* qp = g_q + base + (size_t)(q0 + rowbase) * KD_ + 2 * tg;
        #pragma unroll
        for (int r2 = 0; r2 < 2; r2++) {
            #pragma unroll
            for (int kk = 0; kk < 4; kk++) {
                #pragma unroll
                for (int e = 0; e < 4; e++) {
                    const int row = r2 * 16 + g + (e & 1) * 8;
                    const int off = kk * 16 + (e >> 1) * 8;
                    float2 v = *(const float2*)(qp + (size_t)row * KD_ + off);
                    qf[r2][kk][e] = pack_f16x2(v.x * 0.125f, v.y * 0.125f);
                }
            }
        }
    }

    float oacc[2][8][4];
    #pragma unroll
    for (int r2 = 0; r2 < 2; r2++)
        #pragma unroll
        for (int nt = 0; nt < 8; nt++)
            #pragma unroll
            for (int e = 0; e < 4; e++) oacc[r2][nt][e] = 0.f;
    float lsum[2][2] = {{0.f, 0.f}, {0.f, 0.f}};

    for (int kt = 0; kt < S_; kt += 64) {
        const float* kp = kptr + (size_t)kt * KD_;
        const float* vp = vptr + kt;

        // ---- S = Q K^T (fp16 m16n8k16) ----
        float sc[2][8][4];
        #pragma unroll
        for (int r2 = 0; r2 < 2; r2++)
            #pragma unroll
            for (int nt = 0; nt < 8; nt++)
                #pragma unroll
                for (int e = 0; e < 4; e++) sc[r2][nt][e] = 0.f;

        #pragma unroll
        for (int kk = 0; kk < 4; kk++) {
            uint32_t bf[8][2];
            #pragma unroll
            for (int nt = 0; nt < 8; nt++) {
                float2 a = *(const float2*)(kp + nt * 512 + kk * 16);
                float2 c = *(const float2*)(kp + nt * 512 + kk * 16 + 8);
                bf[nt][0] = pack_f16x2(a.x, a.y);
                bf[nt][1] = pack_f16x2(c.x, c.y);
            }
            #pragma unroll
            for (int r2 = 0; r2 < 2; r2++) {
                #pragma unroll
                for (int nt = 0; nt < 8; nt++)
                    mma_fp16(sc[r2][nt], qf[r2][kk], bf[nt], sc[r2][nt]);
            }
        }

        // ---- P = exp(S - 8): fp16x2 A-fragments in registers ----
        uint32_t pa[2][8][2];
        #pragma unroll
        for (int r2 = 0; r2 < 2; r2++) {
            #pragma unroll
            for (int nt = 0; nt < 8; nt++) {
                const float p0 = __expf(sc[r2][nt][0] - EXP_BIAS);
                const float p1 = __expf(sc[r2][nt][1] - EXP_BIAS);
                const float p2 = __expf(sc[r2][nt][2] - EXP_BIAS);
                const float p3 = __expf(sc[r2][nt][3] - EXP_BIAS);
                lsum[r2][0] += p0 + p1;
                lsum[r2][1] += p2 + p3;
                pa[r2][nt][0] = pack_f16x2(p0, p1);
                pa[r2][nt][1] = pack_f16x2(p2, p3);
            }
        }

        // ---- O += P V (fp16; V^T frags = contiguous float2) ----
        #pragma unroll
        for (int kc = 0; kc < 4; kc++) {
            uint32_t bf[8][2];
            #pragma unroll
            for (int nt = 0; nt < 8; nt++) {
                float2 a = *(const float2*)(vp + (size_t)nt * 8 * S_ + kc * 16);
                float2 c = *(const float2*)(vp + (size_t)nt * 8 * S_ + kc * 16 + 8);
                bf[nt][0] = pack_f16x2(a.x, a.y);
                bf[nt][1] = pack_f16x2(c.x, c.y);
            }
            #pragma unroll
            for (int r2 = 0; r2 < 2; r2++) {
                uint32_t af[4];
                af[0] = pa[r2][2 * kc][0];
                af[1] = pa[r2][2 * kc][1];
                af[2] = pa[r2][2 * kc + 1][0];
                af[3] = pa[r2][2 * kc + 1][1];
                #pragma unroll
                for (int nt = 0; nt < 8; nt++)
                    mma_fp16(oacc[r2][nt], af, bf[nt], oacc[r2][nt]);
            }
        }
    }

    // ---- reduce lsum across quad lanes ----
    #pragma unroll
    for (int r2 = 0; r2 < 2; r2++)
        #pragma unroll
        for (int r = 0; r < 2; r++) {
            lsum[r2][r] += __shfl_xor_sync(0xffffffffu, lsum[r2][r], 1);
            lsum[r2][r] += __shfl_xor_sync(0xffffffffu, lsum[r2][r], 2);
        }

    // ---- normalize + store z (e^-8 bias cancels) ----
    #pragma unroll
    for (int r2 = 0; r2 < 2; r2++) {
        const float inv0 = 1.f / lsum[r2][0];
        const float inv1 = 1.f / lsum[r2][1];
        const int row0 = q0 + rowbase + r2 * 16 + g;
        const int row1 = row0 + 8;
        float* zp0 = g_z + ((size_t)(b * S_ + row0) * H_ + h) * KD_;
        float* zp1 = g_z + ((size_t)(b * S_ + row1) * H_ + h) * KD_;
        #pragma unroll
        for (int nt = 0; nt < 8; nt++) {
            const int col = nt * 8 + 2 * tg;
            *(float2*)(zp0 + col) = make_float2(oacc[r2][nt][0] * inv0,
                                                oacc[r2][nt][1] * inv0);
            *(float2*)(zp1 + col) = make_float2(oacc[r2][nt][2] * inv1,
                                                oacc[r2][nt][3] * inv1);
        }
    }
}

// ---------------------------------------------------------------------------
extern "C" void kernel_launch(void* const* d_in, const int* in_sizes, int n_in,
                              void* d_out, int out_size)
{
    const float* x  = (const float*)d_in[0];
    const float* Wq = (const float*)d_in[1];
    const float* Wk = (const float*)d_in[2];
    const float* Wv = (const float*)d_in[3];
    const float* Wo = (const float*)d_in[4];
    float* out = (float*)d_out;

    static int attr_set = 0;
    if (!attr_set) {
        cudaFuncSetAttribute(gemm_tc<3,0>, cudaFuncAttributeMaxDynamicSharedMemorySize,
                             SMEM_G);
        cudaFuncSetAttribute(gemm_tc<1,0>, cudaFuncAttributeMaxDynamicSharedMemorySize,
                             SMEM_G);
        cudaFuncSetAttribute(gemm_tc<1,1>, cudaFuncAttributeMaxDynamicSharedMemorySize,
                             SMEM_G);
        attr_set = 1;
    }

    // Q,K projection: split-bf16 (exp-amplified path keeps 3-term accuracy)
    gemm_tc<3,0><<<dim3(10, 64), 256, SMEM_G>>>(x, Wq, Wk, Wv, nullptr, 0);
    // V projection: single fp16, transposed output
    gemm_tc<1,0><<<dim3(5, 64), 256, SMEM_G>>>(x, Wq, Wk, Wv, nullptr, 1280);
    // Attention: barrier-free, SMEM-free, direct-LDG fragments
    attn_mma<<<dim3(16, 40), 128>>>();
    // Output projection: single fp16
    gemm_tc<1,1><<<dim3(5, 64), 256, SMEM_G>>>(nullptr, Wo, nullptr, nullptr, out, 0);
}

// round 17
// speedup vs baseline: 2.3789x; 2.3789x over previous
#include <cuda_runtime.h>
#include <math.h>
#include <stdint.h>

#define B_  4
#define S_  2048
#define D_  640
#define H_  10
#define KD_ 64
#define BH_ (B_*H_)
#define BS_ (B_*S_)

// Scratch (allocation-free rule: __device__ globals)
__device__ __align__(16) float g_q[BH_*S_*KD_];   // [b,h,s,kd]
__device__ __align__(16) float g_k[BH_*S_*KD_];   // [b,h,s,kd]
__device__ __align__(16) float g_v[BH_*S_*KD_];   // [b,h,s,kd]
__device__ __align__(16) float g_z[BS_*H_*KD_];   // [b,s,h,kd] = [8192, 640]

// m16n8k16 fp16 mma (all GEMMs, attention S and PV)
__device__ __forceinline__ void mma_fp16(float* d,
                                         const uint32_t* a, const uint32_t* b,
                                         const float* c) {
    asm volatile(
        "mma.sync.aligned.m16n8k16.row.col.f32.f16.f16.f32 "
        "{%0,%1,%2,%3}, {%4,%5,%6,%7}, {%8,%9}, {%10,%11,%12,%13};"
        : "=f"(d[0]), "=f"(d[1]), "=f"(d[2]), "=f"(d[3])
        : "r"(a[0]), "r"(a[1]), "r"(a[2]), "r"(a[3]),
          "r"(b[0]), "r"(b[1]),
          "f"(c[0]), "f"(c[1]), "f"(c[2]), "f"(c[3]));
}

// pack two floats into fp16x2 (lo in low 16 bits)
__device__ __forceinline__ uint32_t pack_f16x2(float lo, float hi) {
    uint32_t r;
    asm("cvt.rn.f16x2.f32 %0, %1, %2;" : "=r"(r) : "f"(hi), "f"(lo));
    return r;
}

__device__ __forceinline__ uint32_t smem_u32(const void* p) {
    uint32_t a;
    asm("{ .reg .u64 t; cvta.to.shared.u64 t, %1; cvt.u32.u64 %0, t; }"
        : "=r"(a) : "l"(p));
    return a;
}
__device__ __forceinline__ void cp_async16(uint32_t dst, const void* src) {
    asm volatile("cp.async.cg.shared.global [%0], [%1], 16;"
                 :: "r"(dst), "l"(src));
}
#define CP_COMMIT()  asm volatile("cp.async.commit_group;" ::: "memory")
#define CP_WAIT(n)   asm volatile("cp.async.wait_group %0;" :: "n"(n) : "memory")

#define PADA 40
#define PADB 132
#define SA_F (128 * PADA)
#define SB_F (32 * PADB)
#define STG_F (SA_F + SB_F)
#define SMEM_G (2 * STG_F * 4)

// ---------------------------------------------------------------------------
// Unified pipelined GEMM on m16n8k16 fp16 tensor cores.
// MODE 0: QKV projection (all 1920 cols, scatter epi into g_q/g_k/g_v)
// MODE 1: output projection (A=g_z device-resolved, direct epi)
// Single-fp16 everywhere: q/k element rounding is softmax-damped (measured
// R12->R14: fp16 staging of q,k moved rel_err by 4e-8); v/out fp16 proven R12.
// ---------------------------------------------------------------------------
template<int MODE>
__global__ __launch_bounds__(256) void gemm_tc(const float* __restrict__ Asrc,
                                               const float* __restrict__ W0,
                                               const float* __restrict__ W1,
                                               const float* __restrict__ W2,
                                               float* __restrict__ outp)
{
    extern __shared__ float smf[];
    const uint32_t sbase = smem_u32(smf);

    const float* Aptr = (MODE == 1) ? (const float*)g_z : Asrc;

    const int tid = threadIdx.x;
    const int wid = tid >> 5;
    const int lid = tid & 31;
    const int g   = lid >> 2;
    const int tg  = lid & 3;
    const int wy  = wid & 3;
    const int wx  = wid >> 2;

    const int m0 = blockIdx.y * 128;
    const int n0 = blockIdx.x * 128;

    const float* W;
    int ha = 0, t = 0;
    if (MODE == 0) {
        t  = n0 / 640;
        W  = (t == 0) ? W0 : ((t == 1) ? W1 : W2);
        ha = (n0 % 640) >> 6;
    } else {
        W = W0;
    }

    auto load_stage = [&](int stage, int k0) {
        const uint32_t sb = sbase + (uint32_t)stage * STG_F * 4;
        #pragma unroll
        for (int i = 0; i < 4; i++) {
            const int e  = i * 256 + tid;
            const int r  = e >> 3;
            const int c4 = (e & 7) * 4;
            cp_async16(sb + (uint32_t)(r * PADA + c4) * 4,
                       Aptr + (size_t)(m0 + r) * D_ + k0 + c4);
        }
        #pragma unroll
        for (int i = 0; i < 4; i++) {
            const int e  = i * 256 + tid;
            const int k  = e >> 5;
            const int c4 = (e & 31) * 4;
            const float* src;
            if (MODE == 0) {
                const int h  = ha + (c4 >> 6);
                const int kd = c4 & 63;
                src = W + ((size_t)h * D_ + k0 + k) * KD_ + kd;
            } else {
                src = W + (size_t)(k0 + k) * D_ + n0 + c4;
            }
            cp_async16(sb + (uint32_t)(SA_F + k * PADB + c4) * 4, src);
        }
        CP_COMMIT();
    };

    float acc[2][8][4];
    #pragma unroll
    for (int r2 = 0; r2 < 2; r2++)
        #pragma unroll
        for (int nt = 0; nt < 8; nt++)
            #pragma unroll
            for (int e = 0; e < 4; e++) acc[r2][nt][e] = 0.f;

    const int NK = D_ / 32;   // 20
    load_stage(0, 0);

    for (int ki = 0; ki < NK; ki++) {
        const int cur = ki & 1;
        if (ki + 1 < NK) {
            load_stage((ki + 1) & 1, (ki + 1) * 32);
            CP_WAIT(1);
        } else {
            CP_WAIT(0);
        }
        __syncthreads();

        const float* As = smf + cur * STG_F;
        const float* Bs = As + SA_F;

        #pragma unroll
        for (int kk = 0; kk < 2; kk++) {
            const int kc = kk * 16;
            uint32_t bh[8][2];
            #pragma unroll
            for (int nt = 0; nt < 8; nt++) {
                const int col = wx * 64 + nt * 8 + g;
                const float v0 = Bs[(kc + 2*tg)     * PADB + col];
                const float v1 = Bs[(kc + 2*tg + 1) * PADB + col];
                const float v2 = Bs[(kc + 2*tg + 8) * PADB + col];
                const float v3 = Bs[(kc + 2*tg + 9) * PADB + col];
                bh[nt][0] = pack_f16x2(v0, v1);
                bh[nt][1] = pack_f16x2(v2, v3);
            }
            #pragma unroll
            for (int r2 = 0; r2 < 2; r2++) {
                const int rb = wy * 32 + r2 * 16;
                uint32_t ah[4];
                {
                    const float2 p0 = *(const float2*)&As[(rb + g)     * PADA + kc + 2*tg];
                    const float2 p1 = *(const float2*)&As[(rb + g + 8) * PADA + kc + 2*tg];
                    const float2 p2 = *(const float2*)&As[(rb + g)     * PADA + kc + 8 + 2*tg];
                    const float2 p3 = *(const float2*)&As[(rb + g + 8) * PADA + kc + 8 + 2*tg];
                    ah[0] = pack_f16x2(p0.x, p0.y);
                    ah[1] = pack_f16x2(p1.x, p1.y);
                    ah[2] = pack_f16x2(p2.x, p2.y);
                    ah[3] = pack_f16x2(p3.x, p3.y);
                }
                #pragma unroll
                for (int nt = 0; nt < 8; nt++)
                    mma_fp16(acc[r2][nt], ah, bh[nt], acc[r2][nt]);
            }
        }
        __syncthreads();
    }

    if (MODE == 0) {
        float* G = (t == 0) ? g_q : ((t == 1) ? g_k : g_v);
        #pragma unroll
        for (int r2 = 0; r2 < 2; r2++) {
            const int m0r = m0 + wy * 32 + r2 * 16 + g;
            #pragma unroll
            for (int nt = 0; nt < 8; nt++) {
                const int col = wx * 64 + nt * 8 + 2 * tg;
                const int n   = n0 + col;
                const int h2  = (n % 640) >> 6;
                const int kd2 = n & 63;
                {
                    const int m = m0r;
                    const int b = m >> 11, s = m & 2047;
                    float* dst = G + (((size_t)(b * H_ + h2) * S_ + s) * KD_) + kd2;
                    *(float2*)dst = make_float2(acc[r2][nt][0], acc[r2][nt][1]);
                }
                {
                    const int m = m0r + 8;
                    const int b = m >> 11, s = m & 2047;
                    float* dst = G + (((size_t)(b * H_ + h2) * S_ + s) * KD_) + kd2;
                    *(float2*)dst = make_float2(acc[r2][nt][2], acc[r2][nt][3]);
                }
            }
        }
    } else {
        #pragma unroll
        for (int r2 = 0; r2 < 2; r2++) {
            const int m0r = m0 + wy * 32 + r2 * 16 + g;
            #pragma unroll
            for (int nt = 0; nt < 8; nt++) {
                const int col = n0 + wx * 64 + nt * 8 + 2 * tg;
                *(float2*)(outp + (size_t)m0r * D_ + col)
                    = make_float2(acc[r2][nt][0], acc[r2][nt][1]);
                *(float2*)(outp + (size_t)(m0r + 8) * D_ + col)
                    = make_float2(acc[r2][nt][2], acc[r2][nt][3]);
            }
        }
    }
}

// ---------------------------------------------------------------------------
// Kernel 2: flash attention — EXACT R14 (best proven): all-fp16 mma, packed
// SMEM, register-resident P, exp bias 8, synchronous staging, 3 CTAs/SM.
// ---------------------------------------------------------------------------
#define PADQ 36
#define PADV 72
#define OFF_QP 0
#define OFF_KP (128 * PADQ)
#define OFF_VP (OFF_KP + 64 * PADQ)
#define SMEM_ATTN ((OFF_VP + 32 * PADV) * 4)   // 36864 bytes

#define EXP_BIAS 8.0f

__global__ __launch_bounds__(128, 3) void attn_mma()
{
    extern __shared__ uint32_t smu[];
    uint32_t* Qp = smu + OFF_QP;
    uint32_t* Kp = smu + OFF_KP;
    uint32_t* Vp = smu + OFF_VP;

    const int tid = threadIdx.x;
    const int wid = tid >> 5;
    const int lid = tid & 31;
    const int g   = lid >> 2;
    const int tg  = lid & 3;

    const int bh = blockIdx.y;
    const int b  = bh / H_;
    const int h  = bh % H_;
    const int q0 = blockIdx.x * 128;
    const size_t base = (size_t)bh * S_ * KD_;

    // Stage Q tile [128 x 64] as packed fp16x2 pairs, pre-scaled
    {
        const float4* qp = (const float4*)(g_q + base + (size_t)q0 * KD_);
        #pragma unroll
        for (int i = 0; i < 16; i++) {
            const int e = i * 128 + tid;
            const int r = e >> 4, p2 = (e & 15) * 2;
            float4 v = qp[e];
            Qp[r * PADQ + p2]     = pack_f16x2(v.x * 0.125f, v.y * 0.125f);
            Qp[r * PADQ + p2 + 1] = pack_f16x2(v.z * 0.125f, v.w * 0.125f);
        }
    }

    float oacc[2][8][4];
    #pragma unroll
    for (int r2 = 0; r2 < 2; r2++)
        #pragma unroll
        for (int nt = 0; nt < 8; nt++)
            #pragma unroll
            for (int e = 0; e < 4; e++) oacc[r2][nt][e] = 0.f;
    float lsum[2][2] = {{0.f, 0.f}, {0.f, 0.f}};

    const int rowbase = wid * 32;

    for (int kt = 0; kt < S_; kt += 64) {
        __syncthreads();
        // Stage K [64 x 64] as packed fp16x2 kd-pairs
        {
            const float4* kp = (const float4*)(g_k + base + (size_t)kt * KD_);
            #pragma unroll
            for (int i = 0; i < 8; i++) {
                const int e = i * 128 + tid;
                const int r = e >> 4, p2 = (e & 15) * 2;
                float4 kv = kp[e];
                Kp[r * PADQ + p2]     = pack_f16x2(kv.x, kv.y);
                Kp[r * PADQ + p2 + 1] = pack_f16x2(kv.z, kv.w);
            }
        }
        // Stage V as key-pair packed fp16x2
        {
            const float4* vp4 = (const float4*)(g_v + base + (size_t)kt * KD_);
            #pragma unroll
            for (int i = 0; i < 4; i++) {
                const int e  = i * 128 + tid;
                const int pi = e >> 4, c4 = (e & 15) * 4;
                float4 va = vp4[(2 * pi)     * 16 + (c4 >> 2)];
                float4 vb = vp4[(2 * pi + 1) * 16 + (c4 >> 2)];
                uint4 w;
                w.x = pack_f16x2(va.x, vb.x);
                w.y = pack_f16x2(va.y, vb.y);
                w.z = pack_f16x2(va.z, vb.z);
                w.w = pack_f16x2(va.w, vb.w);
                *(uint4*)&Vp[pi * PADV + c4] = w;
            }
        }
        __syncthreads();

        // ---- S = Q K^T (fp16 m16n8k16: 4 k-chunks of 16) ----
        float sc[2][8][4];
        #pragma unroll
        for (int r2 = 0; r2 < 2; r2++)
            #pragma unroll
            for (int nt = 0; nt < 8; nt++)
                #pragma unroll
                for (int e = 0; e < 4; e++) sc[r2][nt][e] = 0.f;

        #pragma unroll
        for (int kk = 0; kk < 4; kk++) {
            uint32_t bf[8][2];
            #pragma unroll
            for (int nt = 0; nt < 8; nt++) {
                bf[nt][0] = Kp[(nt * 8 + g) * PADQ + kk * 8 + tg];
                bf[nt][1] = Kp[(nt * 8 + g) * PADQ + kk * 8 + tg + 4];
            }
            #pragma unroll
            for (int r2 = 0; r2 < 2; r2++) {
                const int rb = rowbase + r2 * 16;
                uint32_t af[4];
                af[0] = Qp[(rb + g)     * PADQ + kk * 8 + tg];
                af[1] = Qp[(rb + g + 8) * PADQ + kk * 8 + tg];
                af[2] = Qp[(rb + g)     * PADQ + kk * 8 + tg + 4];
                af[3] = Qp[(rb + g + 8) * PADQ + kk * 8 + tg + 4];
                #pragma unroll
                for (int nt = 0; nt < 8; nt++)
                    mma_fp16(sc[r2][nt], af, bf[nt], sc[r2][nt]);
            }
        }

        // ---- P = exp(S - 8): fp16x2 A-fragments in registers ----
        uint32_t pa[2][8][2];
        #pragma unroll
        for (int r2 = 0; r2 < 2; r2++) {
            #pragma unroll
            for (int nt = 0; nt < 8; nt++) {
                const float p0 = __expf(sc[r2][nt][0] - EXP_BIAS);
                const float p1 = __expf(sc[r2][nt][1] - EXP_BIAS);
                const float p2 = __expf(sc[r2][nt][2] - EXP_BIAS);
                const float p3 = __expf(sc[r2][nt][3] - EXP_BIAS);
                lsum[r2][0] += p0 + p1;
                lsum[r2][1] += p2 + p3;
                pa[r2][nt][0] = pack_f16x2(p0, p1);
                pa[r2][nt][1] = pack_f16x2(p2, p3);
            }
        }

        // ---- O += P V (fp16) ----
        #pragma unroll
        for (int kc = 0; kc < 4; kc++) {
            uint32_t bf[8][2];
            #pragma unroll
            for (int nt = 0; nt < 8; nt++) {
                bf[nt][0] = Vp[(kc * 8 + tg)     * PADV + nt * 8 + g];
                bf[nt][1] = Vp[(kc * 8 + tg + 4) * PADV + nt * 8 + g];
            }
            #pragma unroll
            for (int r2 = 0; r2 < 2; r2++) {
                uint32_t af[4];
                af[0] = pa[r2][2 * kc][0];
                af[1] = pa[r2][2 * kc][1];
                af[2] = pa[r2][2 * kc + 1][0];
                af[3] = pa[r2][2 * kc + 1][1];
                #pragma unroll
                for (int nt = 0; nt < 8; nt++)
                    mma_fp16(oacc[r2][nt], af, bf[nt], oacc[r2][nt]);
            }
        }
    }

    // ---- reduce lsum across quad lanes ----
    #pragma unroll
    for (int r2 = 0; r2 < 2; r2++)
        #pragma unroll
        for (int r = 0; r < 2; r++) {
            lsum[r2][r] += __shfl_xor_sync(0xffffffffu, lsum[r2][r], 1);
            lsum[r2][r] += __shfl_xor_sync(0xffffffffu, lsum[r2][r], 2);
        }

    // ---- normalize + store z (e^-8 bias cancels) ----
    #pragma unroll
    for (int r2 = 0; r2 < 2; r2++) {
        const float inv0 = 1.f / lsum[r2][0];
        const float inv1 = 1.f / lsum[r2][1];
        const int row0 = q0 + rowbase + r2 * 16 + g;
        const int row1 = row0 + 8;
        float* zp0 = g_z + ((size_t)(b * S_ + row0) * H_ + h) * KD_;
        float* zp1 = g_z + ((size_t)(b * S_ + row1) * H_ + h) * KD_;
        #pragma unroll
        for (int nt = 0; nt < 8; nt++) {
            const int col = nt * 8 + 2 * tg;
            *(float2*)(zp0 + col) = make_float2(oacc[r2][nt][0] * inv0,
                                                oacc[r2][nt][1] * inv0);
            *(float2*)(zp1 + col) = make_float2(oacc[r2][nt][2] * inv1,
                                                oacc[r2][nt][3] * inv1);
        }
    }
}

// ---------------------------------------------------------------------------
extern "C" void kernel_launch(void* const* d_in, const int* in_sizes, int n_in,
                              void* d_out, int out_size)
{
    const float* x  = (const float*)d_in[0];
    const float* Wq = (const float*)d_in[1];
    const float* Wk = (const float*)d_in[2];
    const float* Wv = (const float*)d_in[3];
    const float* Wo = (const float*)d_in[4];
    float* out = (float*)d_out;

    static int attr_set = 0;
    if (!attr_set) {
        cudaFuncSetAttribute(attn_mma, cudaFuncAttributeMaxDynamicSharedMemorySize,
                             SMEM_ATTN);
        cudaFuncSetAttribute(gemm_tc<0>, cudaFuncAttributeMaxDynamicSharedMemorySize,
                             SMEM_G);
        cudaFuncSetAttribute(gemm_tc<1>, cudaFuncAttributeMaxDynamicSharedMemorySize,
                             SMEM_G);
        attr_set = 1;
    }

    // QKV projection: all 1920 cols, single fp16, one launch
    gemm_tc<0><<<dim3(15, 64), 256, SMEM_G>>>(x, Wq, Wk, Wv, nullptr);
    // Attention (exact R14)
    attn_mma<<<dim3(16, 40), 128, SMEM_ATTN>>>();
    // Output projection: single fp16
    gemm_tc<1><<<dim3(5, 64), 256, SMEM_G>>>(nullptr, Wo, nullptr, nullptr, out);
}